// round 2
// baseline (speedup 1.0000x reference)
#include <cuda_runtime.h>
#include <cstdint>

// ---------------------------------------------------------------------------
// R-NEM cell, fully fused fp32 SIMT pipeline.
//   K=8, FC=256, LAST=128, B=2048, M=1024, H=512
//   rows1 = B*K = 16384, rows2 = B*K*(K-1) = 114688
// ---------------------------------------------------------------------------

#define FCN   256
#define LASTN 128
#define HDIM  512
#define MDIM  1024
#define NR1   16384
#define NR2   114688
#define BKT   16

// scratch (device globals; allocation in kernel_launch is forbidden)
__device__ float g_s1[NR1 * FCN];      // 16 MB
__device__ float g_core[NR2 * FCN];    // 117 MB
__device__ float g_eff[NR1 * FCN];     // 16 MB

// ---------------------------------------------------------------------------
// Kernel 1: s1 = relu(LN(state @ enc_w + enc_b))      [16384 x 256], K=512
// tile: 128 rows x 256 cols, 512 threads (32x16), 8x8 per thread
// ---------------------------------------------------------------------------
__global__ __launch_bounds__(512, 1) void k_enc(
    const float* __restrict__ state, const float* __restrict__ W,
    const float* __restrict__ bias, const float* __restrict__ gam,
    const float* __restrict__ bet)
{
    __shared__ float As[BKT][132];
    __shared__ float Bs[BKT][FCN];
    const int x = threadIdx.x, y = threadIdx.y;
    const int tid = y * 32 + x;
    const int R0 = blockIdx.x * 128;
    const int lk = tid & 15, lr = tid >> 4;

    float acc[8][8];
#pragma unroll
    for (int r = 0; r < 8; r++)
#pragma unroll
        for (int c = 0; c < 8; c++) acc[r][c] = 0.f;

    for (int kt = 0; kt < HDIM; kt += BKT) {
#pragma unroll
        for (int p = 0; p < 4; p++)
            As[lk][lr + 32 * p] = state[(size_t)(R0 + lr + 32 * p) * HDIM + kt + lk];
#pragma unroll
        for (int p = 0; p < 2; p++) {
            int idx = tid + 512 * p;
            int kk = idx >> 6, n4 = idx & 63;
            *(float4*)&Bs[kk][n4 * 4] =
                *(const float4*)&W[(size_t)(kt + kk) * FCN + n4 * 4];
        }
        __syncthreads();
#pragma unroll
        for (int kk = 0; kk < BKT; kk++) {
            float a[8];
            float4 a0 = *(const float4*)&As[kk][y * 8];
            float4 a1 = *(const float4*)&As[kk][y * 8 + 4];
            a[0]=a0.x; a[1]=a0.y; a[2]=a0.z; a[3]=a0.w;
            a[4]=a1.x; a[5]=a1.y; a[6]=a1.z; a[7]=a1.w;
            float b[8];
#pragma unroll
            for (int c = 0; c < 8; c++) b[c] = Bs[kk][x + 32 * c];
#pragma unroll
            for (int r = 0; r < 8; r++)
#pragma unroll
                for (int c = 0; c < 8; c++) acc[r][c] += a[r] * b[c];
        }
        __syncthreads();
    }

    float bi[8], ga[8], be[8];
#pragma unroll
    for (int c = 0; c < 8; c++) {
        int col = x + 32 * c;
        bi[c] = bias[col]; ga[c] = gam[col]; be[c] = bet[col];
    }
#pragma unroll
    for (int r = 0; r < 8; r++) {
        int row = R0 + y * 8 + r;
        float v[8], s = 0.f, s2 = 0.f;
#pragma unroll
        for (int c = 0; c < 8; c++) { v[c] = acc[r][c] + bi[c]; s += v[c]; s2 += v[c] * v[c]; }
#pragma unroll
        for (int o = 16; o; o >>= 1) {
            s  += __shfl_xor_sync(0xffffffffu, s,  o);
            s2 += __shfl_xor_sync(0xffffffffu, s2, o);
        }
        float mu = s * (1.f / FCN);
        float var = s2 * (1.f / FCN) - mu * mu;
        float rs = rsqrtf(var + 1e-5f);
#pragma unroll
        for (int c = 0; c < 8; c++) {
            float o2 = (v[c] - mu) * rs * ga[c] + be[c];
            g_s1[(size_t)row * FCN + x + 32 * c] = fmaxf(o2, 0.f);
        }
    }
}

// ---------------------------------------------------------------------------
// Kernel 2: core = relu(LN(concat(s1[p], s1[q]) @ core_w + b))  [114688x256], K=512
// A never materialized: virtual row v -> p = v/7 (focus), q = peer row.
// ---------------------------------------------------------------------------
__global__ __launch_bounds__(512, 1) void k_core(
    const float* __restrict__ W, const float* __restrict__ bias,
    const float* __restrict__ gam, const float* __restrict__ bet)
{
    __shared__ float As[BKT][132];
    __shared__ float Bs[BKT][FCN];
    const int x = threadIdx.x, y = threadIdx.y;
    const int tid = y * 32 + x;
    const int R0 = blockIdx.x * 128;
    const int lk = tid & 15, lr = tid >> 4;

    int prow[4], qrow[4];
#pragma unroll
    for (int p = 0; p < 4; p++) {
        int v = R0 + lr + 32 * p;
        int pr = v / 7;
        int jj = v - pr * 7;
        int i = pr & 7;
        int j = jj + (jj >= i ? 1 : 0);
        prow[p] = pr;
        qrow[p] = (pr & ~7) + j;
    }

    float acc[8][8];
#pragma unroll
    for (int r = 0; r < 8; r++)
#pragma unroll
        for (int c = 0; c < 8; c++) acc[r][c] = 0.f;

    for (int kt = 0; kt < 2 * FCN; kt += BKT) {
        const bool first = kt < FCN;
        const int kc = first ? (kt + lk) : (kt + lk - FCN);
#pragma unroll
        for (int p = 0; p < 4; p++) {
            int src = first ? prow[p] : qrow[p];
            As[lk][lr + 32 * p] = g_s1[(size_t)src * FCN + kc];
        }
#pragma unroll
        for (int p = 0; p < 2; p++) {
            int idx = tid + 512 * p;
            int kk = idx >> 6, n4 = idx & 63;
            *(float4*)&Bs[kk][n4 * 4] =
                *(const float4*)&W[(size_t)(kt + kk) * FCN + n4 * 4];
        }
        __syncthreads();
#pragma unroll
        for (int kk = 0; kk < BKT; kk++) {
            float a[8];
            float4 a0 = *(const float4*)&As[kk][y * 8];
            float4 a1 = *(const float4*)&As[kk][y * 8 + 4];
            a[0]=a0.x; a[1]=a0.y; a[2]=a0.z; a[3]=a0.w;
            a[4]=a1.x; a[5]=a1.y; a[6]=a1.z; a[7]=a1.w;
            float b[8];
#pragma unroll
            for (int c = 0; c < 8; c++) b[c] = Bs[kk][x + 32 * c];
#pragma unroll
            for (int r = 0; r < 8; r++)
#pragma unroll
                for (int c = 0; c < 8; c++) acc[r][c] += a[r] * b[c];
        }
        __syncthreads();
    }

    float bi[8], ga[8], be[8];
#pragma unroll
    for (int c = 0; c < 8; c++) {
        int col = x + 32 * c;
        bi[c] = bias[col]; ga[c] = gam[col]; be[c] = bet[col];
    }
#pragma unroll
    for (int r = 0; r < 8; r++) {
        int row = R0 + y * 8 + r;
        float v[8], s = 0.f, s2 = 0.f;
#pragma unroll
        for (int c = 0; c < 8; c++) { v[c] = acc[r][c] + bi[c]; s += v[c]; s2 += v[c] * v[c]; }
#pragma unroll
        for (int o = 16; o; o >>= 1) {
            s  += __shfl_xor_sync(0xffffffffu, s,  o);
            s2 += __shfl_xor_sync(0xffffffffu, s2, o);
        }
        float mu = s * (1.f / FCN);
        float var = s2 * (1.f / FCN) - mu * mu;
        float rs = rsqrtf(var + 1e-5f);
#pragma unroll
        for (int c = 0; c < 8; c++) {
            float o2 = (v[c] - mu) * rs * ga[c] + be[c];
            g_core[(size_t)row * FCN + x + 32 * c] = fmaxf(o2, 0.f);
        }
    }
}

// ---------------------------------------------------------------------------
// Kernel 3: fused ctx + attention + effect reduction.
//   ctx  = relu(LN(core @ ctx_w + b))       (never materialized)
//   att  = sigmoid(tanh(LN(core @ att1_w + b)) @ att2_w + att2_b)
//   eff[v/7] += att * ctx                   (7 rows per group, in-block)
// tile: 56 virtual rows (= 8 effect groups), 448 threads (32x14), 4x(8+4)/thread
// ---------------------------------------------------------------------------
__global__ __launch_bounds__(448, 1) void k_eff(
    const float* __restrict__ ctxW, const float* __restrict__ ctx_b,
    const float* __restrict__ ctx_g, const float* __restrict__ ctx_bb,
    const float* __restrict__ a1W,  const float* __restrict__ a1_b,
    const float* __restrict__ att_g, const float* __restrict__ att_bb,
    const float* __restrict__ a2W,  const float* __restrict__ a2_b)
{
    __shared__ float As[BKT][60];
    __shared__ float Bc[BKT][FCN];
    __shared__ float Ba[BKT][LASTN];
    __shared__ float s_eff[8][FCN];
    const int x = threadIdx.x, y = threadIdx.y;
    const int tid = y * 32 + x;
    const int R0 = blockIdx.x * 56;
    const int lk = tid & 15, lr = tid >> 4;

    for (int idx = tid; idx < 8 * FCN; idx += 448) ((float*)s_eff)[idx] = 0.f;

    float ac[4][8], aa[4][4];
#pragma unroll
    for (int r = 0; r < 4; r++) {
#pragma unroll
        for (int c = 0; c < 8; c++) ac[r][c] = 0.f;
#pragma unroll
        for (int c = 0; c < 4; c++) aa[r][c] = 0.f;
    }

    for (int kt = 0; kt < FCN; kt += BKT) {
#pragma unroll
        for (int p = 0; p < 2; p++)
            As[lk][lr + 28 * p] = g_core[(size_t)(R0 + lr + 28 * p) * FCN + kt + lk];
        for (int idx = tid; idx < BKT * FCN / 4; idx += 448) {
            int kk = idx >> 6, n4 = idx & 63;
            *(float4*)&Bc[kk][n4 * 4] =
                *(const float4*)&ctxW[(size_t)(kt + kk) * FCN + n4 * 4];
        }
        for (int idx = tid; idx < BKT * LASTN / 4; idx += 448) {
            int kk = idx >> 5, n4 = idx & 31;
            *(float4*)&Ba[kk][n4 * 4] =
                *(const float4*)&a1W[(size_t)(kt + kk) * LASTN + n4 * 4];
        }
        __syncthreads();
#pragma unroll
        for (int kk = 0; kk < BKT; kk++) {
            float4 av = *(const float4*)&As[kk][y * 4];
            float a[4] = {av.x, av.y, av.z, av.w};
            float bc[8], ba[4];
#pragma unroll
            for (int c = 0; c < 8; c++) bc[c] = Bc[kk][x + 32 * c];
#pragma unroll
            for (int c = 0; c < 4; c++) ba[c] = Ba[kk][x + 32 * c];
#pragma unroll
            for (int r = 0; r < 4; r++) {
#pragma unroll
                for (int c = 0; c < 8; c++) ac[r][c] += a[r] * bc[c];
#pragma unroll
                for (int c = 0; c < 4; c++) aa[r][c] += a[r] * ba[c];
            }
        }
        __syncthreads();
    }

    float cb[8], cg[8], cbb[8];
#pragma unroll
    for (int c = 0; c < 8; c++) {
        int col = x + 32 * c;
        cb[c] = ctx_b[col]; cg[c] = ctx_g[col]; cbb[c] = ctx_bb[col];
    }
    float ab[4], ag[4], abb[4], aw[4];
#pragma unroll
    for (int c = 0; c < 4; c++) {
        int col = x + 32 * c;
        ab[c] = a1_b[col]; ag[c] = att_g[col]; abb[c] = att_bb[col]; aw[c] = a2W[col];
    }
    const float a2b = a2_b[0];

#pragma unroll
    for (int r = 0; r < 4; r++) {
        int lrow = y * 4 + r;
        // ctx LN + relu
        float v[8], s = 0.f, s2 = 0.f;
#pragma unroll
        for (int c = 0; c < 8; c++) { v[c] = ac[r][c] + cb[c]; s += v[c]; s2 += v[c] * v[c]; }
#pragma unroll
        for (int o = 16; o; o >>= 1) {
            s  += __shfl_xor_sync(0xffffffffu, s,  o);
            s2 += __shfl_xor_sync(0xffffffffu, s2, o);
        }
        float mu = s * (1.f / FCN);
        float rs = rsqrtf(s2 * (1.f / FCN) - mu * mu + 1e-5f);
        float cv[8];
#pragma unroll
        for (int c = 0; c < 8; c++)
            cv[c] = fmaxf((v[c] - mu) * rs * cg[c] + cbb[c], 0.f);

        // attention LN (over 128) + tanh + dot(att2_w) + sigmoid
        float w[4], t = 0.f, t2 = 0.f;
#pragma unroll
        for (int c = 0; c < 4; c++) { w[c] = aa[r][c] + ab[c]; t += w[c]; t2 += w[c] * w[c]; }
#pragma unroll
        for (int o = 16; o; o >>= 1) {
            t  += __shfl_xor_sync(0xffffffffu, t,  o);
            t2 += __shfl_xor_sync(0xffffffffu, t2, o);
        }
        float mua = t * (1.f / LASTN);
        float rsa = rsqrtf(t2 * (1.f / LASTN) - mua * mua + 1e-5f);
        float dot = 0.f;
#pragma unroll
        for (int c = 0; c < 4; c++) {
            float h = tanhf((w[c] - mua) * rsa * ag[c] + abb[c]);
            dot += h * aw[c];
        }
#pragma unroll
        for (int o = 16; o; o >>= 1) dot += __shfl_xor_sync(0xffffffffu, dot, o);
        float att = 1.f / (1.f + expf(-(dot + a2b)));

        int g = lrow / 7;   // 56-row tile = 8 whole groups of 7
#pragma unroll
        for (int c = 0; c < 8; c++)
            atomicAdd(&s_eff[g][x + 32 * c], att * cv[c]);
    }
    __syncthreads();
    for (int idx = tid; idx < 8 * FCN; idx += 448) {
        int gg = idx >> 8, col = idx & 255;
        g_eff[(size_t)(blockIdx.x * 8 + gg) * FCN + col] = s_eff[gg][col];
    }
}

// ---------------------------------------------------------------------------
// Kernel 4: new_state = concat(s1, effect, x) @ out_w + out_b   [16384x256], K=1536
// A gathered from three sources per k-segment; writes both output copies.
// ---------------------------------------------------------------------------
__global__ __launch_bounds__(512, 1) void k_out(
    const float* __restrict__ xin, const float* __restrict__ W,
    const float* __restrict__ bias, float* __restrict__ out, int dup)
{
    __shared__ float As[BKT][132];
    __shared__ float Bs[BKT][FCN];
    const int x = threadIdx.x, y = threadIdx.y;
    const int tid = y * 32 + x;
    const int R0 = blockIdx.x * 128;
    const int lk = tid & 15, lr = tid >> 4;

    float acc[8][8];
#pragma unroll
    for (int r = 0; r < 8; r++)
#pragma unroll
        for (int c = 0; c < 8; c++) acc[r][c] = 0.f;

    for (int kt = 0; kt < 2 * FCN + MDIM; kt += BKT) {
        const int kc = kt + lk;
#pragma unroll
        for (int p = 0; p < 4; p++) {
            int row = R0 + lr + 32 * p;
            float vv;
            if (kc < FCN)          vv = g_s1[(size_t)row * FCN + kc];
            else if (kc < 2 * FCN) vv = g_eff[(size_t)row * FCN + kc - FCN];
            else                   vv = xin[(size_t)row * MDIM + kc - 2 * FCN];
            As[lk][lr + 32 * p] = vv;
        }
#pragma unroll
        for (int p = 0; p < 2; p++) {
            int idx = tid + 512 * p;
            int kk = idx >> 6, n4 = idx & 63;
            *(float4*)&Bs[kk][n4 * 4] =
                *(const float4*)&W[(size_t)(kt + kk) * FCN + n4 * 4];
        }
        __syncthreads();
#pragma unroll
        for (int kk = 0; kk < BKT; kk++) {
            float a[8];
            float4 a0 = *(const float4*)&As[kk][y * 8];
            float4 a1 = *(const float4*)&As[kk][y * 8 + 4];
            a[0]=a0.x; a[1]=a0.y; a[2]=a0.z; a[3]=a0.w;
            a[4]=a1.x; a[5]=a1.y; a[6]=a1.z; a[7]=a1.w;
            float b[8];
#pragma unroll
            for (int c = 0; c < 8; c++) b[c] = Bs[kk][x + 32 * c];
#pragma unroll
            for (int r = 0; r < 8; r++)
#pragma unroll
                for (int c = 0; c < 8; c++) acc[r][c] += a[r] * b[c];
        }
        __syncthreads();
    }

    float bi[8];
#pragma unroll
    for (int c = 0; c < 8; c++) bi[c] = bias[x + 32 * c];
#pragma unroll
    for (int r = 0; r < 8; r++) {
        int row = R0 + y * 8 + r;
#pragma unroll
        for (int c = 0; c < 8; c++) {
            float o2 = acc[r][c] + bi[c];
            size_t off = (size_t)row * FCN + x + 32 * c;
            out[off] = o2;
            if (dup) out[(size_t)NR1 * FCN + off] = o2;
        }
    }
}

// ---------------------------------------------------------------------------
extern "C" void kernel_launch(void* const* d_in, const int* in_sizes, int n_in,
                              void* d_out, int out_size) {
    const float* x      = (const float*)d_in[0];
    const float* state  = (const float*)d_in[1];
    const float* enc_w  = (const float*)d_in[2];
    const float* enc_b  = (const float*)d_in[3];
    const float* enc_g  = (const float*)d_in[4];
    const float* enc_bb = (const float*)d_in[5];
    const float* core_w = (const float*)d_in[6];
    const float* core_b = (const float*)d_in[7];
    const float* core_g = (const float*)d_in[8];
    const float* core_bb= (const float*)d_in[9];
    const float* ctx_w  = (const float*)d_in[10];
    const float* ctx_b  = (const float*)d_in[11];
    const float* ctx_g  = (const float*)d_in[12];
    const float* ctx_bb = (const float*)d_in[13];
    const float* att1_w = (const float*)d_in[14];
    const float* att1_b = (const float*)d_in[15];
    const float* att_g  = (const float*)d_in[16];
    const float* att_bb = (const float*)d_in[17];
    const float* att2_w = (const float*)d_in[18];
    const float* att2_b = (const float*)d_in[19];
    const float* out_w  = (const float*)d_in[20];
    const float* out_b  = (const float*)d_in[21];
    float* out = (float*)d_out;
    int dup = (out_size >= 2 * NR1 * FCN) ? 1 : 0;

    k_enc <<<NR1 / 128, dim3(32, 16)>>>(state, enc_w, enc_b, enc_g, enc_bb);
    k_core<<<NR2 / 128, dim3(32, 16)>>>(core_w, core_b, core_g, core_bb);
    k_eff <<<NR2 / 56,  dim3(32, 14)>>>(ctx_w, ctx_b, ctx_g, ctx_bb,
                                        att1_w, att1_b, att_g, att_bb,
                                        att2_w, att2_b);
    k_out <<<NR1 / 128, dim3(32, 16)>>>(x, out_w, out_b, out, dup);
}